// round 1
// baseline (speedup 1.0000x reference)
#include <cuda_runtime.h>
#include <cuda_fp16.h>

// CapsuleLayer dynamic routing, GB300 sm_103a.
// Strategy: materialize u_hat once in fp16 (256 MB, __device__ scratch),
// then stream it for the 5 routing contractions (s-pass x3, b-update x2).
//
// Shapes: B=128, U=8, C=2048, J=32, S=16, T=J*S=512.
//   x[b,u,c]            f32
//   W[0,c,j,s,u]        f32
//   u_hat[c][b][t]      f16   (t = j*16+s)
//   out v[b,j,s,1]      f32

#define Bsz 128
#define Uu  8
#define Cc  2048
#define Jj  32
#define Ss  16
#define Tt  512          // Jj*Ss
#define SPLIT 8
#define CPS (Cc / SPLIT) // 256

// Scratch (module-load allocated; no cudaMalloc anywhere)
__device__ __half g_uhat[(size_t)Cc * Bsz * Tt];   // 256 MB
__device__ float  g_spart[SPLIT * Bsz * Tt];       // 2 MB split-K partials for s
__device__ float  g_v[Bsz * Tt];
__device__ float  g_b[Cc * Jj];
__device__ float  g_c[Cc * Jj];

// ---------------------------------------------------------------------------
// u_hat[c,b,t] = sum_u W[c,t,u] * x[b,u,c]; also zeroes routing logits b.
// One block per c. W row (8 floats/thread) lives in registers; x column
// (128x8) staged in smem, read back as broadcast LDS.128.
// ---------------------------------------------------------------------------
__global__ void __launch_bounds__(Tt) k_uhat(const float* __restrict__ x,
                                             const float* __restrict__ W) {
    int c = blockIdx.x, t = threadIdx.x;
    if (t < Jj) g_b[c * Jj + t] = 0.0f;

    __shared__ __align__(16) float xs[Bsz * Uu];
    for (int i = t; i < Bsz * Uu; i += Tt) {
        int b = i >> 3, u = i & 7;
        xs[i] = x[((size_t)b * Uu + u) * Cc + c];
    }
    const float4* Wp =
        reinterpret_cast<const float4*>(W + (size_t)c * (Tt * Uu) + t * Uu);
    float4 w0 = Wp[0], w1 = Wp[1];
    __syncthreads();

    __half* out = g_uhat + (size_t)c * (Bsz * Tt) + t;
#pragma unroll 4
    for (int b = 0; b < Bsz; ++b) {
        const float4* xp = reinterpret_cast<const float4*>(xs + b * Uu);
        float4 x0 = xp[0], x1 = xp[1];
        float acc = w0.x * x0.x + w0.y * x0.y + w0.z * x0.z + w0.w * x0.w
                  + w1.x * x1.x + w1.y * x1.y + w1.z * x1.z + w1.w * x1.w;
        out[(size_t)b * Tt] = __float2half_rn(acc);
    }
}

// ---------------------------------------------------------------------------
// c[:,j] = softmax over C of b[:,j]. One block per j (tiny kernel).
// ---------------------------------------------------------------------------
__global__ void __launch_bounds__(256) k_softmax() {
    int j = blockIdx.x, t = threadIdx.x;
    __shared__ float red[256];

    float m = -1e30f;
    for (int c = t; c < Cc; c += 256) m = fmaxf(m, g_b[c * Jj + j]);
    red[t] = m; __syncthreads();
    for (int o = 128; o > 0; o >>= 1) {
        if (t < o) red[t] = fmaxf(red[t], red[t + o]);
        __syncthreads();
    }
    m = red[0]; __syncthreads();

    float sum = 0.0f;
    for (int c = t; c < Cc; c += 256) {
        float e = expf(g_b[c * Jj + j] - m);
        g_c[c * Jj + j] = e;
        sum += e;
    }
    red[t] = sum; __syncthreads();
    for (int o = 128; o > 0; o >>= 1) {
        if (t < o) red[t] += red[t + o];
        __syncthreads();
    }
    float inv = 1.0f / red[0];
    for (int c = t; c < Cc; c += 256) g_c[c * Jj + j] *= inv;
}

// ---------------------------------------------------------------------------
// s-pass (split-K over c): s_part[cs][b][t] = sum_{c in slice} c[c,j]*u_hat[c,b,t]
// grid = (SPLIT, B). Streams u_hat exactly once, coalesced 1KB rows.
// ---------------------------------------------------------------------------
__global__ void __launch_bounds__(Tt) k_spass() {
    int cs = blockIdx.x, b = blockIdx.y, t = threadIdx.x;
    int c0 = cs * CPS;

    __shared__ float cw[CPS * Jj];  // 32 KB coupling-coef slice [c][j]
    for (int i = t; i < CPS * Jj; i += Tt) cw[i] = g_c[c0 * Jj + i];
    __syncthreads();

    int j = t >> 4;
    const __half* up = g_uhat + (size_t)c0 * (Bsz * Tt) + (size_t)b * Tt + t;
    float acc = 0.0f;
#pragma unroll 8
    for (int ci = 0; ci < CPS; ++ci)
        acc += cw[ci * Jj + j] * __half2float(up[(size_t)ci * (Bsz * Tt)]);
    g_spart[(cs * Bsz + b) * Tt + t] = acc;
}

// ---------------------------------------------------------------------------
// squash: sum split-K partials, norm over J per (b,s) (faithful to the ref's
// axis=1 squash), write v (and the final output on the last iteration).
// ---------------------------------------------------------------------------
__global__ void __launch_bounds__(Tt) k_squash(float* outp) {
    int b = blockIdx.x, t = threadIdx.x;
    float s = 0.0f;
#pragma unroll
    for (int k = 0; k < SPLIT; ++k) s += g_spart[(k * Bsz + b) * Tt + t];

    __shared__ float sv[Tt];
    sv[t] = s; __syncthreads();

    int si = t & (Ss - 1);
    float msq = 0.0f;
#pragma unroll
    for (int j = 0; j < Jj; ++j) { float vv = sv[j * Ss + si]; msq += vv * vv; }
    float mag = sqrtf(msq);
    float f   = msq / (1.0f + msq) / mag;
    float v   = s * f;
    g_v[b * Tt + t] = v;
    if (outp) outp[b * Tt + t] = v;
}

// ---------------------------------------------------------------------------
// b-update: b[c,j] += (1/B) * sum_{b,s} u_hat[c,b,j,s] * v[b,j,s]
// One block per c; shuffle-reduce over the 16 s-lanes.
// ---------------------------------------------------------------------------
__global__ void __launch_bounds__(Tt) k_bpass() {
    int c = blockIdx.x, t = threadIdx.x;
    const __half* up = g_uhat + (size_t)c * (Bsz * Tt) + t;
    const float*  vp = g_v + t;
    float acc = 0.0f;
#pragma unroll 8
    for (int b = 0; b < Bsz; ++b)
        acc += __half2float(up[(size_t)b * Tt]) * vp[b * Tt];
    acc += __shfl_xor_sync(0xffffffffu, acc, 1);
    acc += __shfl_xor_sync(0xffffffffu, acc, 2);
    acc += __shfl_xor_sync(0xffffffffu, acc, 4);
    acc += __shfl_xor_sync(0xffffffffu, acc, 8);
    if ((t & (Ss - 1)) == 0)
        g_b[c * Jj + (t >> 4)] += acc * (1.0f / Bsz);
}

// ---------------------------------------------------------------------------
extern "C" void kernel_launch(void* const* d_in, const int* in_sizes, int n_in,
                              void* d_out, int out_size) {
    // x has 2,097,152 elements; W has 8,388,608 — disambiguate by size.
    const float* x;
    const float* W;
    if (in_sizes[0] == Bsz * Uu * Cc) { x = (const float*)d_in[0]; W = (const float*)d_in[1]; }
    else                              { x = (const float*)d_in[1]; W = (const float*)d_in[0]; }
    float* out = (float*)d_out;

    k_uhat<<<Cc, Tt>>>(x, W);
    for (int it = 0; it < 3; ++it) {
        k_softmax<<<Jj, 256>>>();
        k_spass<<<dim3(SPLIT, Bsz), Tt>>>();
        k_squash<<<Bsz, Tt>>>(it == 2 ? out : nullptr);
        if (it < 2) k_bpass<<<Cc, Tt>>>();   // 3rd b-update is dead in the ref
    }
}

// round 2
// speedup vs baseline: 3.4496x; 3.4496x over previous
#include <cuda_runtime.h>
#include <cuda_fp16.h>
#include <cstdint>

// CapsuleLayer dynamic routing on GB300 — u_hat is NEVER materialized.
// u_hat[b,c,j,s] = sum_u W[c,j,s,u] x[b,u,c] is rank-8 in (b)x(t); every
// routing contraction becomes a small-operand GEMM (all fp16 operands L2-resident):
//   s[b,t]   = sum_{c,u} Xbc[u][b][c] * (cw[j(t)][c] * Wh[u][t][c])   (tensor cores)
//   db[c,j]  = (1/B) sum_u sum_{t in j} Wh[u][t][c] * (Xcb[u][c][:] @ v[:,t])
// B=128, U=8, C=2048, J=32, S=16, T=512.

#define Bsz 128
#define Uu  8
#define Cc  2048
#define Jj  32
#define Ss  16
#define Tt  512

// ---- scratch (__device__, no allocs) ----
__device__ __half g_Wh [(size_t)Uu * Tt * Cc];     // [u][t][c] 16 MB
__device__ __half g_Xbc[(size_t)Uu * Bsz * Cc];    // [u][b][c]  4 MB
__device__ __half g_Xcb[(size_t)Uu * Cc * Bsz];    // [u][c][b]  4 MB
__device__ __half g_cwh[(size_t)Jj * Cc];          // [j][c]
__device__ __half g_vh [(size_t)Tt * Bsz];         // [t][b]
__device__ float  g_spart[(size_t)32 * Bsz * Tt];  // 32 K-slices of s  (8 MB)
__device__ float  g_bpart[(size_t)32 * Cc * 8];    // (ttile*8+u) x [c][jl] (2 MB)
__device__ float  g_b[Cc * Jj];
__device__ float  g_c[Cc * Jj];

#define MMA16816(d, A0, A1, A2, A3, B0, B1)                                   \
  asm volatile(                                                               \
      "mma.sync.aligned.m16n8k16.row.col.f32.f16.f16.f32 "                    \
      "{%0,%1,%2,%3},{%4,%5,%6,%7},{%8,%9},{%0,%1,%2,%3};"                    \
      : "+f"(d[0]), "+f"(d[1]), "+f"(d[2]), "+f"(d[3])                        \
      : "r"(A0), "r"(A1), "r"(A2), "r"(A3), "r"(B0), "r"(B1))

static __device__ __forceinline__ uint32_t lds_u32(const __half* p) {
    return *reinterpret_cast<const uint32_t*>(p);
}

// ---------------------------------------------------------------------------
// prep: Wh[u][t][c] = half(W[c][t][u])  (smem tile transpose)
// ---------------------------------------------------------------------------
__global__ void __launch_bounds__(256) k_prep_w(const float* __restrict__ W) {
    __shared__ __half sh[128][130];
    int c0 = blockIdx.x * 128, t0 = blockIdx.y * 16, tid = threadIdx.x;
#pragma unroll
    for (int l = 0; l < 16; ++l) {
        int idx4 = tid + l * 256;        // 4096 float4
        int c = idx4 >> 5, f = (idx4 & 31) * 4;
        float4 v = *reinterpret_cast<const float4*>(
            W + (size_t)(c0 + c) * (Tt * Uu) + t0 * Uu + f);
        sh[c][f + 0] = __float2half_rn(v.x);
        sh[c][f + 1] = __float2half_rn(v.y);
        sh[c][f + 2] = __float2half_rn(v.z);
        sh[c][f + 3] = __float2half_rn(v.w);
    }
    __syncthreads();
#pragma unroll
    for (int l = 0; l < 64; ++l) {
        int idx = tid + l * 256;         // 16384
        int oc = idx & 127, orow = idx >> 7;
        int u = orow >> 4, tt = orow & 15;
        g_Wh[((size_t)u * Tt + t0 + tt) * Cc + c0 + oc] = sh[oc][tt * Uu + u];
    }
}

// Xbc[u][b][c] = half(x[b][u][c])  (outer-dim permute, c stays contiguous)
__global__ void __launch_bounds__(256) k_prep_x1(const float* __restrict__ x) {
    int g = blockIdx.x * 256 + threadIdx.x;     // 512K float4
    int c4 = (g & 511) * 4, rest = g >> 9;      // rest = b*8+u
    int b = rest >> 3, u = rest & 7;
    float4 v = *reinterpret_cast<const float4*>(x + (size_t)rest * Cc + c4);
    __half2 h0 = __floats2half2_rn(v.x, v.y);
    __half2 h1 = __floats2half2_rn(v.z, v.w);
    uint2 o = {*reinterpret_cast<uint32_t*>(&h0), *reinterpret_cast<uint32_t*>(&h1)};
    *reinterpret_cast<uint2*>(&g_Xbc[((size_t)u * Bsz + b) * Cc + c4]) = o;
}

// Xcb[u][c][b] = half(x[b][u][c])  (smem transpose)
__global__ void __launch_bounds__(256) k_prep_x2(const float* __restrict__ x) {
    __shared__ __half xs[128][130];
    int u = blockIdx.y, c0 = blockIdx.x * 128, tid = threadIdx.x;
#pragma unroll
    for (int l = 0; l < 16; ++l) {
        int idx4 = tid + l * 256;
        int b = idx4 >> 5, cc = (idx4 & 31) * 4;
        float4 v = *reinterpret_cast<const float4*>(
            x + ((size_t)b * Uu + u) * Cc + c0 + cc);
        xs[b][cc + 0] = __float2half_rn(v.x);
        xs[b][cc + 1] = __float2half_rn(v.y);
        xs[b][cc + 2] = __float2half_rn(v.z);
        xs[b][cc + 3] = __float2half_rn(v.w);
    }
    __syncthreads();
#pragma unroll
    for (int l = 0; l < 64; ++l) {
        int idx = tid + l * 256;
        int bb = idx & 127, cr = idx >> 7;
        g_Xcb[((size_t)u * Cc + c0 + cr) * Bsz + bb] = xs[bb][cr];
    }
}

__global__ void k_zero() {
    int i = blockIdx.x * 1024 + threadIdx.x;
    if (i < Cc * Jj) g_b[i] = 0.0f;
}

// ---------------------------------------------------------------------------
// softmax over C per j; writes cwh[j][c] fp16
// ---------------------------------------------------------------------------
__global__ void __launch_bounds__(256) k_softmax() {
    int j = blockIdx.x, t = threadIdx.x;
    __shared__ float red[256];
    float m = -1e30f;
    for (int c = t; c < Cc; c += 256) m = fmaxf(m, g_b[c * Jj + j]);
    red[t] = m; __syncthreads();
    for (int o = 128; o > 0; o >>= 1) {
        if (t < o) red[t] = fmaxf(red[t], red[t + o]);
        __syncthreads();
    }
    m = red[0]; __syncthreads();
    float sum = 0.0f;
    for (int c = t; c < Cc; c += 256) {
        float e = expf(g_b[c * Jj + j] - m);
        g_c[c * Jj + j] = e;
        sum += e;
    }
    red[t] = sum; __syncthreads();
    for (int o = 128; o > 0; o >>= 1) {
        if (t < o) red[t] += red[t + o];
        __syncthreads();
    }
    float inv = 1.0f / red[0];
    for (int c = t; c < Cc; c += 256)
        g_cwh[(size_t)j * Cc + c] = __float2half_rn(g_c[c * Jj + j] * inv);
}

// ---------------------------------------------------------------------------
// GEMM1: s[b][t] = sum_c Xbc[u][b][c] * (cw[j(t)][c]*Wh[u][t][c]),
// split over (u, c/512). grid (mt=2, nt=4, z=32), 256 thr (8 warps: 4m x 2n).
// Partials -> g_spart[z][b][t].
// ---------------------------------------------------------------------------
__global__ void __launch_bounds__(256) k_sgemm() {
    __shared__ __half As[64 * 72];      // [b-local][c-local]
    __shared__ __half Bs[128 * 72];     // [t-local][c-local] (cw-weighted)
    int tid = threadIdx.x, lane = tid & 31, w = tid >> 5;
    int wm = w & 3, wn = w >> 2;
    int b0 = blockIdx.x * 64, t0 = blockIdx.y * 128;
    int z = blockIdx.z, u = z >> 2, c0 = (z & 3) * 512;

    float acc[8][4];
#pragma unroll
    for (int i = 0; i < 8; ++i)
#pragma unroll
        for (int q = 0; q < 4; ++q) acc[i][q] = 0.0f;

    for (int kc = 0; kc < 8; ++kc) {
        int cb = c0 + kc * 64;
#pragma unroll
        for (int l = 0; l < 2; ++l) {            // A: 512 int4
            int idx = tid + l * 256;
            int r = idx >> 3, k8 = (idx & 7) * 8;
            *reinterpret_cast<int4*>(&As[r * 72 + k8]) =
                *reinterpret_cast<const int4*>(
                    &g_Xbc[((size_t)u * Bsz + b0 + r) * Cc + cb + k8]);
        }
#pragma unroll
        for (int l = 0; l < 4; ++l) {            // B: 1024 int4, cw-weighted
            int idx = tid + l * 256;
            int r = idx >> 3, k8 = (idx & 7) * 8;
            int t = t0 + r, j = t >> 4;
            int4 wv = *reinterpret_cast<const int4*>(
                &g_Wh[((size_t)u * Tt + t) * Cc + cb + k8]);
            int4 cv = *reinterpret_cast<const int4*>(
                &g_cwh[(size_t)j * Cc + cb + k8]);
            __half2* wp = reinterpret_cast<__half2*>(&wv);
            const __half2* cp = reinterpret_cast<const __half2*>(&cv);
#pragma unroll
            for (int q = 0; q < 4; ++q) wp[q] = __hmul2(wp[q], cp[q]);
            *reinterpret_cast<int4*>(&Bs[r * 72 + k8]) = wv;
        }
        __syncthreads();
#pragma unroll
        for (int ks = 0; ks < 4; ++ks) {
            int kk = ks * 16;
            const __half* ab = &As[(wm * 16 + (lane >> 2)) * 72 + kk + (lane & 3) * 2];
            uint32_t a0 = lds_u32(ab);
            uint32_t a1 = lds_u32(ab + 8 * 72);
            uint32_t a2 = lds_u32(ab + 8);
            uint32_t a3 = lds_u32(ab + 8 * 72 + 8);
#pragma unroll
            for (int nf = 0; nf < 8; ++nf) {
                const __half* bb =
                    &Bs[(wn * 64 + nf * 8 + (lane >> 2)) * 72 + kk + (lane & 3) * 2];
                uint32_t bb0 = lds_u32(bb);
                uint32_t bb1 = lds_u32(bb + 8);
                MMA16816(acc[nf], a0, a1, a2, a3, bb0, bb1);
            }
        }
        __syncthreads();
    }
    int r0 = b0 + wm * 16 + (lane >> 2);
    float* base = g_spart + (size_t)z * (Bsz * Tt);
#pragma unroll
    for (int nf = 0; nf < 8; ++nf) {
        int col = t0 + wn * 64 + nf * 8 + (lane & 3) * 2;
        float* p = base + r0 * Tt + col;
        p[0] = acc[nf][0]; p[1] = acc[nf][1];
        p[8 * Tt] = acc[nf][2]; p[8 * Tt + 1] = acc[nf][3];
    }
}

// ---------------------------------------------------------------------------
// reduce partials + squash (norm over J per (b,s), faithful to ref axis).
// writes vh[t][b] fp16 and (last iter) the fp32 output.
// ---------------------------------------------------------------------------
__global__ void __launch_bounds__(Tt) k_squash(float* outp) {
    int b = blockIdx.x, t = threadIdx.x;
    float s = 0.0f;
#pragma unroll
    for (int sl = 0; sl < 32; ++sl) s += g_spart[(size_t)sl * (Bsz * Tt) + b * Tt + t];
    __shared__ float sv[Tt];
    sv[t] = s; __syncthreads();
    int si = t & (Ss - 1);
    float msq = 0.0f;
#pragma unroll
    for (int j = 0; j < Jj; ++j) { float vv = sv[j * Ss + si]; msq += vv * vv; }
    float mag = sqrtf(msq);
    float v = s * (msq / (1.0f + msq) / mag);
    g_vh[(size_t)t * Bsz + b] = __float2half_rn(v);
    if (outp) outp[b * Tt + t] = v;
}

// ---------------------------------------------------------------------------
// GEMM2 + fused b-reduce epilogue:
//   P[c][t] = sum_b Xcb[u][c][b] * v[b][t];  partial_b[c][jl] = sum_{t in j} Wh[u][t][c]*P[c][t]
// grid (ct=16, tt=4, u=8), 256 thr (8 warps along M).
// ---------------------------------------------------------------------------
__global__ void __launch_bounds__(256) k_pgemm() {
    __shared__ __half sm[2 * 128 * 72];          // As | Bs, reused as Ws[128][136]
    __half* As = sm;
    __half* Bs = sm + 128 * 72;
    int tid = threadIdx.x, lane = tid & 31, w = tid >> 5;
    int c0 = blockIdx.x * 128, t0 = blockIdx.y * 128, u = blockIdx.z;

    float acc[16][4];
#pragma unroll
    for (int i = 0; i < 16; ++i)
#pragma unroll
        for (int q = 0; q < 4; ++q) acc[i][q] = 0.0f;

#pragma unroll
    for (int chunk = 0; chunk < 2; ++chunk) {
        int kb = chunk * 64;
#pragma unroll
        for (int l = 0; l < 4; ++l) {
            int idx = tid + l * 256;
            int r = idx >> 3, k8 = (idx & 7) * 8;
            *reinterpret_cast<int4*>(&As[r * 72 + k8]) =
                *reinterpret_cast<const int4*>(
                    &g_Xcb[((size_t)u * Cc + c0 + r) * Bsz + kb + k8]);
            *reinterpret_cast<int4*>(&Bs[r * 72 + k8]) =
                *reinterpret_cast<const int4*>(
                    &g_vh[(size_t)(t0 + r) * Bsz + kb + k8]);
        }
        __syncthreads();
#pragma unroll
        for (int ks = 0; ks < 4; ++ks) {
            int kk = ks * 16;
            const __half* ab = &As[(w * 16 + (lane >> 2)) * 72 + kk + (lane & 3) * 2];
            uint32_t a0 = lds_u32(ab);
            uint32_t a1 = lds_u32(ab + 8 * 72);
            uint32_t a2 = lds_u32(ab + 8);
            uint32_t a3 = lds_u32(ab + 8 * 72 + 8);
#pragma unroll
            for (int nf = 0; nf < 16; ++nf) {
                const __half* bb =
                    &Bs[(nf * 8 + (lane >> 2)) * 72 + kk + (lane & 3) * 2];
                uint32_t bb0 = lds_u32(bb);
                uint32_t bb1 = lds_u32(bb + 8);
                MMA16816(acc[nf], a0, a1, a2, a3, bb0, bb1);
            }
        }
        __syncthreads();
    }

    // epilogue: stage Wh tile [t][c] (stride 136), fused weighted reduce
    __half* Ws = sm;
#pragma unroll
    for (int l = 0; l < 8; ++l) {
        int idx = tid + l * 256;                 // 2048 int4
        int r = idx >> 4, k8 = (idx & 15) * 8;
        *reinterpret_cast<int4*>(&Ws[r * 136 + k8]) =
            *reinterpret_cast<const int4*>(
                &g_Wh[((size_t)u * Tt + t0 + r) * Cc + c0 + k8]);
    }
    __syncthreads();

    float baccA[8], baccB[8];
#pragma unroll
    for (int k = 0; k < 8; ++k) { baccA[k] = 0.0f; baccB[k] = 0.0f; }
    int ccA = w * 16 + (lane >> 2), ccB = ccA + 8;
#pragma unroll
    for (int nf = 0; nf < 16; ++nf) {
        int tl = nf * 8 + (lane & 3) * 2;
        float w00 = __half2float(Ws[tl * 136 + ccA]);
        float w01 = __half2float(Ws[(tl + 1) * 136 + ccA]);
        float w10 = __half2float(Ws[tl * 136 + ccB]);
        float w11 = __half2float(Ws[(tl + 1) * 136 + ccB]);
        int jl = nf >> 1;
        baccA[jl] += acc[nf][0] * w00 + acc[nf][1] * w01;
        baccB[jl] += acc[nf][2] * w10 + acc[nf][3] * w11;
    }
#pragma unroll
    for (int k = 0; k < 8; ++k) {
        baccA[k] += __shfl_xor_sync(0xffffffffu, baccA[k], 1);
        baccA[k] += __shfl_xor_sync(0xffffffffu, baccA[k], 2);
        baccB[k] += __shfl_xor_sync(0xffffffffu, baccB[k], 1);
        baccB[k] += __shfl_xor_sync(0xffffffffu, baccB[k], 2);
    }
    if ((lane & 3) == 0) {
        int slice = blockIdx.y * 8 + u;
        float* pA = g_bpart + ((size_t)slice * Cc + c0 + ccA) * 8;
        float* pB = g_bpart + ((size_t)slice * Cc + c0 + ccB) * 8;
#pragma unroll
        for (int jl = 0; jl < 8; ++jl) { pA[jl] = baccA[jl]; pB[jl] = baccB[jl]; }
    }
}

// b[c,j] += (1/B) * sum_u partials
__global__ void __launch_bounds__(256) k_bupd() {
    int id = blockIdx.x * 256 + threadIdx.x;    // 65536
    int c = id >> 5, j = id & 31;
    int tt = j >> 3, jl = j & 7;
    float s = 0.0f;
#pragma unroll
    for (int u = 0; u < Uu; ++u)
        s += g_bpart[((size_t)(tt * 8 + u) * Cc + c) * 8 + jl];
    g_b[c * Jj + j] += s * (1.0f / Bsz);
}

// ---------------------------------------------------------------------------
extern "C" void kernel_launch(void* const* d_in, const int* in_sizes, int n_in,
                              void* d_out, int out_size) {
    const float* x;
    const float* W;
    if (in_sizes[0] == Bsz * Uu * Cc) { x = (const float*)d_in[0]; W = (const float*)d_in[1]; }
    else                              { x = (const float*)d_in[1]; W = (const float*)d_in[0]; }
    float* out = (float*)d_out;

    k_prep_w<<<dim3(Cc / 128, Tt / 16), 256>>>(W);
    k_prep_x1<<<2048, 256>>>(x);
    k_prep_x2<<<dim3(Cc / 128, Uu), 256>>>(x);
    k_zero<<<64, 1024>>>();

    for (int it = 0; it < 3; ++it) {
        k_softmax<<<Jj, 256>>>();
        k_sgemm<<<dim3(2, 4, 32), 256>>>();
        k_squash<<<Bsz, Tt>>>(it == 2 ? out : nullptr);
        if (it < 2) {
            k_pgemm<<<dim3(16, 4, 8), 256>>>();
            k_bupd<<<256, 256>>>();
        }
    }
}